// round 1
// baseline (speedup 1.0000x reference)
#include <cuda_runtime.h>

// GroupWiseLinearProjector:
//   x  : [16, 512, 64, 64] f32
//   Wg : [16, 512, 512]    f32   (phase p = (h%4)*4 + (w%4), Wg[p][o][c])
//   out: [16, 512, 64, 64] f32
//   out[b,o,h,w] = sum_c x[b,c,h,w] * Wg[p(h,w), o, c]
//
// Strategy: 16 grouped GEMMs, one block per (b, phase, o-tile 128, pixel-tile 64).
// Register-blocked FFMA GEMM with double-buffered shared memory.

#define CIN  512
#define COUT 512
#define HH   64
#define WW   64
#define KC   16     // K chunk
#define BO   128    // o per block
#define BPX  64     // pixels per block (4 i-rows x 16 j-cols)
#define NTHREADS 256

#define WPAD (BO + 4)    // 132 floats/row -> 528B (16B multiple)
#define XPAD (BPX + 4)   // 68  floats/row -> 272B (16B multiple)

__global__ __launch_bounds__(NTHREADS)
void gwlp_kernel(const float* __restrict__ x,
                 const float* __restrict__ Wg,
                 float* __restrict__ out)
{
    __shared__ float Ws[2][KC][WPAD];
    __shared__ float Xs[2][KC][XPAD];

    const int bid     = blockIdx.x;
    const int pixtile = bid & 3;          // 4 pixel tiles (i0 = pixtile*4)
    const int otile   = (bid >> 2) & 3;   // 4 o tiles
    const int phase   = (bid >> 4) & 15;  // 16 phases
    const int b       = bid >> 8;         // 16 batches
    const int r  = phase >> 2;            // h % 4
    const int q  = phase & 3;             // w % 4
    const int i0 = pixtile * 4;           // h4 tile start
    const int o0 = otile * BO;

    const int tid = threadIdx.x;

    // ---- global load mappings ----
    // W: elem = tid + v*256; o = elem>>2; k4 = (elem&3)*4  (float4 along c)
    const float* Wbase = Wg + ((size_t)phase * COUT + o0) * CIN;

    // X: j = tid&15 (w4 col), ck = tid>>4 (k within chunk); 4 i-rows each
    const int lj  = tid & 15;
    const int lck = tid >> 4;
    const float* xbase = x + (((size_t)b * CIN) * HH + (size_t)(i0 * 4 + r)) * WW
                           + (size_t)(q + 4 * lj);

    float4 wreg[2];
    float  xreg[4];

    // ---- prefetch + store chunk 0 ----
    {
        #pragma unroll
        for (int v = 0; v < 2; v++) {
            int elem = tid + v * NTHREADS;
            int o  = elem >> 2;
            int k4 = (elem & 3) << 2;
            wreg[v] = *(const float4*)(Wbase + (size_t)o * CIN + k4);
        }
        const float* p = xbase + (size_t)lck * (HH * WW);
        #pragma unroll
        for (int il = 0; il < 4; il++)
            xreg[il] = p[il * 4 * WW];

        #pragma unroll
        for (int v = 0; v < 2; v++) {
            int elem = tid + v * NTHREADS;
            int o  = elem >> 2;
            int k4 = (elem & 3) << 2;
            Ws[0][k4 + 0][o] = wreg[v].x;
            Ws[0][k4 + 1][o] = wreg[v].y;
            Ws[0][k4 + 2][o] = wreg[v].z;
            Ws[0][k4 + 3][o] = wreg[v].w;
        }
        #pragma unroll
        for (int il = 0; il < 4; il++)
            Xs[0][lck][il * 16 + lj] = xreg[il];
    }
    __syncthreads();

    // ---- compute mapping ----
    const int og = tid & 15;   // o group: o = o0 + og*8 + 0..7
    const int pg = tid >> 4;   // px group: px = pg*4 + 0..3

    float acc[4][8];
    #pragma unroll
    for (int i = 0; i < 4; i++)
        #pragma unroll
        for (int j = 0; j < 8; j++)
            acc[i][j] = 0.0f;

    int buf = 0;
    for (int c0 = 0; c0 < CIN; c0 += KC) {
        const int cn = c0 + KC;
        const bool has_next = (cn < CIN);

        // prefetch next chunk into registers
        if (has_next) {
            #pragma unroll
            for (int v = 0; v < 2; v++) {
                int elem = tid + v * NTHREADS;
                int o  = elem >> 2;
                int k4 = (elem & 3) << 2;
                wreg[v] = *(const float4*)(Wbase + (size_t)o * CIN + cn + k4);
            }
            const float* p = xbase + (size_t)(cn + lck) * (HH * WW);
            #pragma unroll
            for (int il = 0; il < 4; il++)
                xreg[il] = p[il * 4 * WW];
        }

        // compute on current buffer
        #pragma unroll
        for (int k = 0; k < KC; k++) {
            float4 xv = *(const float4*)&Xs[buf][k][pg * 4];
            float4 wa = *(const float4*)&Ws[buf][k][og * 8];
            float4 wb = *(const float4*)&Ws[buf][k][og * 8 + 4];
            float xw[4] = {xv.x, xv.y, xv.z, xv.w};
            float wv[8] = {wa.x, wa.y, wa.z, wa.w, wb.x, wb.y, wb.z, wb.w};
            #pragma unroll
            for (int pp = 0; pp < 4; pp++)
                #pragma unroll
                for (int oo = 0; oo < 8; oo++)
                    acc[pp][oo] = fmaf(xw[pp], wv[oo], acc[pp][oo]);
        }

        // publish next chunk
        if (has_next) {
            #pragma unroll
            for (int v = 0; v < 2; v++) {
                int elem = tid + v * NTHREADS;
                int o  = elem >> 2;
                int k4 = (elem & 3) << 2;
                Ws[buf ^ 1][k4 + 0][o] = wreg[v].x;
                Ws[buf ^ 1][k4 + 1][o] = wreg[v].y;
                Ws[buf ^ 1][k4 + 2][o] = wreg[v].z;
                Ws[buf ^ 1][k4 + 3][o] = wreg[v].w;
            }
            #pragma unroll
            for (int il = 0; il < 4; il++)
                Xs[buf ^ 1][lck][il * 16 + lj] = xreg[il];
            __syncthreads();
            buf ^= 1;
        }
    }

    // ---- epilogue: scatter to out[b, o, h, w] ----
    #pragma unroll
    for (int pp = 0; pp < 4; pp++) {
        int px = pg * 4 + pp;
        int il = px >> 4;
        int j  = px & 15;
        int h  = (i0 + il) * 4 + r;
        int w  = q + 4 * j;
        float* op = out + (((size_t)b * COUT + o0 + og * 8) * HH + h) * WW + w;
        #pragma unroll
        for (int oo = 0; oo < 8; oo++)
            op[(size_t)oo * HH * WW] = acc[pp][oo];
    }
}

extern "C" void kernel_launch(void* const* d_in, const int* in_sizes, int n_in,
                              void* d_out, int out_size)
{
    const float* x  = (const float*)d_in[0];   // [16, 512, 64, 64]
    const float* Wg = (const float*)d_in[1];   // [16, 512, 512]
    float* out = (float*)d_out;                // [16, 512, 64, 64]

    // 16 b * 16 phase * 4 o-tiles * 4 pixel-tiles = 4096 blocks
    gwlp_kernel<<<4096, NTHREADS>>>(x, Wg, out);
}

// round 3
// speedup vs baseline: 3.2346x; 3.2346x over previous
#include <cuda_runtime.h>
#include <cuda_bf16.h>
#include <cstdint>

// ============================================================================
// GroupWiseLinearProjector via mma.sync bf16x3-split GEMM (compute_103-safe)
//   x  : [16, 512, 64, 64] f32
//   Wg : [16, 512, 512]    f32  (phase p = (h%4)*4 + (w%4))
//   out[b,o,h,w] = sum_c x[b,c,h,w] * Wg[p,o,c]
// Per (b, phase): D[512 o, 256 px] = W[512,512] * X[256 px, 512]^T
// fp32 = bf16_hi + bf16_lo;  D = Wh*Xh + Wh*Xl + Wl*Xh  (fp32 accum)
// ============================================================================

#define B_   16
#define CIN  512
#define COUT 512
#define NPX  256
#define KC   64          // K chunk (64 bf16 = 128B row, SW128 swizzle)
#define NSTAGE 8         // 512 / 64

// ---------------- scratch (device globals; no allocation) ----------------
__device__ __align__(256) unsigned short g_Xh[B_ * 16 * NPX * CIN];   // 64MB
__device__ __align__(256) unsigned short g_Xl[B_ * 16 * NPX * CIN];   // 64MB
__device__ __align__(256) unsigned short g_Wh[16 * COUT * CIN];       // 8MB
__device__ __align__(256) unsigned short g_Wl[16 * COUT * CIN];       // 8MB
__device__ __align__(256) float g_tmp[B_ * 16 * COUT * NPX];          // 134MB

// ---------------- helpers ----------------
__device__ __forceinline__ uint32_t smem_to_u32(const void* p) {
    uint32_t a;
    asm("{ .reg .u64 t; cvta.to.shared.u64 t, %1; cvt.u32.u64 %0, t; }"
        : "=r"(a) : "l"(p));
    return a;
}
__device__ __forceinline__ void cp_async16(uint32_t dst, const void* src) {
    asm volatile("cp.async.cg.shared.global [%0], [%1], 16;"
                 :: "r"(dst), "l"(src) : "memory");
}
#define CP_COMMIT() asm volatile("cp.async.commit_group;" ::: "memory")
#define CP_WAIT(n)  asm volatile("cp.async.wait_group %0;" :: "n"(n) : "memory")

__device__ __forceinline__ void ldmx4(uint32_t* r, uint32_t addr) {
    asm volatile("ldmatrix.sync.aligned.m8n8.x4.shared.b16 {%0,%1,%2,%3}, [%4];"
                 : "=r"(r[0]), "=r"(r[1]), "=r"(r[2]), "=r"(r[3]) : "r"(addr));
}
__device__ __forceinline__ void mma16816(float* d, const uint32_t* a,
                                         uint32_t b0, uint32_t b1) {
    asm volatile(
        "mma.sync.aligned.m16n8k16.row.col.f32.bf16.bf16.f32 "
        "{%0,%1,%2,%3}, {%4,%5,%6,%7}, {%8,%9}, {%0,%1,%2,%3};"
        : "+f"(d[0]), "+f"(d[1]), "+f"(d[2]), "+f"(d[3])
        : "r"(a[0]), "r"(a[1]), "r"(a[2]), "r"(a[3]), "r"(b0), "r"(b1));
}
#define SWZ(off) ((uint32_t)(off) ^ ((((uint32_t)(off)) >> 3) & 0x70))

// ============================================================================
// Pass 1a: W -> Wh/Wl bf16 (same layout [ph][o][c])
// ============================================================================
__global__ __launch_bounds__(256)
void convert_w_kernel(const float* __restrict__ Wg) {
    size_t gt = (size_t)blockIdx.x * 256 + threadIdx.x;
    const float4* src = reinterpret_cast<const float4*>(Wg) + gt * 2;
    float4 a = src[0], b = src[1];
    float v[8] = {a.x, a.y, a.z, a.w, b.x, b.y, b.z, b.w};
    unsigned short hb[8], lb[8];
#pragma unroll
    for (int i = 0; i < 8; i++) {
        __nv_bfloat16 h = __float2bfloat16(v[i]);
        float hf = __bfloat162float(h);
        __nv_bfloat16 l = __float2bfloat16(v[i] - hf);
        hb[i] = __bfloat16_as_ushort(h);
        lb[i] = __bfloat16_as_ushort(l);
    }
    uint4 uh, ul;
    uh.x = hb[0] | (uint32_t)hb[1] << 16;  uh.y = hb[2] | (uint32_t)hb[3] << 16;
    uh.z = hb[4] | (uint32_t)hb[5] << 16;  uh.w = hb[6] | (uint32_t)hb[7] << 16;
    ul.x = lb[0] | (uint32_t)lb[1] << 16;  ul.y = lb[2] | (uint32_t)lb[3] << 16;
    ul.z = lb[4] | (uint32_t)lb[5] << 16;  ul.w = lb[6] | (uint32_t)lb[7] << 16;
    *reinterpret_cast<uint4*>(g_Wh + gt * 8) = uh;
    *reinterpret_cast<uint4*>(g_Wl + gt * 8) = ul;
}

// ============================================================================
// Pass 1b: x -> Xh/Xl bf16 in [b][phase][px][c] (K-major)
// ============================================================================
__global__ __launch_bounds__(256)
void convert_x_kernel(const float* __restrict__ x) {
    __shared__ float sin[64][68];
    int bid = blockIdx.x;                 // 16 * 64 * 8 = 8192
    int cc = bid & 7;
    int h  = (bid >> 3) & 63;
    int b  = bid >> 9;
    int c0 = cc * 64;
    int t  = threadIdx.x;

    const float* src = x + (((size_t)b * CIN + c0) * 64 + h) * 64;
    {
        int c  = t >> 2;
        int f0 = t & 3;
#pragma unroll
        for (int j = 0; j < 4; j++) {
            float4 v = *reinterpret_cast<const float4*>(src + (size_t)c * 4096 + (f0 + 4 * j) * 4);
            *reinterpret_cast<float4*>(&sin[c][(f0 + 4 * j) * 4]) = v;
        }
    }
    __syncthreads();

    int p   = t >> 2;
    int q   = p >> 4;
    int w4  = p & 15;
    int cc4 = t & 3;
    int r   = h & 3;
    int h4  = h >> 2;

    unsigned short hb[16], lb[16];
#pragma unroll
    for (int i = 0; i < 16; i++) {
        float v = sin[cc4 * 16 + i][q + 4 * w4];
        __nv_bfloat16 hh = __float2bfloat16(v);
        float hf = __bfloat162float(hh);
        __nv_bfloat16 ll = __float2bfloat16(v - hf);
        hb[i] = __bfloat16_as_ushort(hh);
        lb[i] = __bfloat16_as_ushort(ll);
    }

    int phase = r * 4 + q;
    int px    = h4 * 16 + w4;
    size_t off = (((size_t)(b * 16 + phase) * NPX) + px) * CIN + c0 + cc4 * 16;

    uint4 u0, u1;
    u0.x = hb[0] | (uint32_t)hb[1] << 16;   u0.y = hb[2]  | (uint32_t)hb[3] << 16;
    u0.z = hb[4] | (uint32_t)hb[5] << 16;   u0.w = hb[6]  | (uint32_t)hb[7] << 16;
    u1.x = hb[8] | (uint32_t)hb[9] << 16;   u1.y = hb[10] | (uint32_t)hb[11] << 16;
    u1.z = hb[12]| (uint32_t)hb[13] << 16;  u1.w = hb[14] | (uint32_t)hb[15] << 16;
    *reinterpret_cast<uint4*>(g_Xh + off)     = u0;
    *reinterpret_cast<uint4*>(g_Xh + off + 8) = u1;
    u0.x = lb[0] | (uint32_t)lb[1] << 16;   u0.y = lb[2]  | (uint32_t)lb[3] << 16;
    u0.z = lb[4] | (uint32_t)lb[5] << 16;   u0.w = lb[6]  | (uint32_t)lb[7] << 16;
    u1.x = lb[8] | (uint32_t)lb[9] << 16;   u1.y = lb[10] | (uint32_t)lb[11] << 16;
    u1.z = lb[12]| (uint32_t)lb[13] << 16;  u1.w = lb[14] | (uint32_t)lb[15] << 16;
    *reinterpret_cast<uint4*>(g_Xl + off)     = u0;
    *reinterpret_cast<uint4*>(g_Xl + off + 8) = u1;
}

// ============================================================================
// Pass 2: GEMM via mma.sync, CTA = (b, phase, otile 128, ptile 128)
//   8 warps: mw = wid&3 (32 o-rows), nw = wid>>2 (64 px)
//   smem stage (64KB): Wh | Wl | Xh | Xl, each 128x64 bf16 swizzled; x2 buf
// ============================================================================
#define STAGE_BYTES 65536
#define T_WH 0
#define T_WL 16384
#define T_XH 32768
#define T_XL 49152

__global__ __launch_bounds__(256, 1)
void gwlp_mma_kernel() {
    extern __shared__ __align__(1024) char sm[];
    const uint32_t smb = smem_to_u32(sm);

    const int t   = threadIdx.x;
    const int wid = t >> 5;
    const int lid = t & 31;
    const int mw  = wid & 3;    // o sub-tile (32 rows)
    const int nw  = wid >> 2;   // px sub-tile (64 rows)

    const int bid   = blockIdx.x;   // 2048
    const int otile = bid & 3;
    const int ptile = (bid >> 2) & 1;
    const int phase = (bid >> 3) & 15;
    const int b     = bid >> 7;
    const int o0    = otile * 128;
    const int px0   = ptile * 128;

    const unsigned short* whp = g_Wh + ((size_t)phase * COUT + o0) * CIN;
    const unsigned short* wlp = g_Wl + ((size_t)phase * COUT + o0) * CIN;
    const unsigned short* xhp = g_Xh + ((size_t)(b * 16 + phase) * NPX + px0) * CIN;
    const unsigned short* xlp = g_Xl + ((size_t)(b * 16 + phase) * NPX + px0) * CIN;

    // ---- stage loader (cp.async): 1024 16B-granules per tensor ----
    auto load_stage = [&](int s, int buf) {
        const uint32_t sb = smb + (uint32_t)buf * STAGE_BYTES;
        const int ce = s * KC;
#pragma unroll
        for (int i = 0; i < 4; i++) {
            int gi  = t + i * 256;
            int row = gi >> 3, g = gi & 7;
            uint32_t d = sb + SWZ(row * 128 + g * 16);
            size_t so = (size_t)row * CIN + ce + g * 8;
            cp_async16(d + T_WH, whp + so);
            cp_async16(d + T_WL, wlp + so);
            cp_async16(d + T_XH, xhp + so);
            cp_async16(d + T_XL, xlp + so);
        }
        CP_COMMIT();
    };

    // ---- per-lane ldmatrix address components ----
    const int lr = lid & 15;
    const int cb = lid >> 4;
    uint32_t a_off[2], a_key[2];
#pragma unroll
    for (int mt = 0; mt < 2; mt++) {
        int row = mw * 32 + mt * 16 + lr;
        a_off[mt] = (uint32_t)row * 128;
        a_key[mt] = (uint32_t)(row & 7) << 4;
    }
    uint32_t b_off[4], b_key[4];
#pragma unroll
    for (int j = 0; j < 4; j++) {
        int row = nw * 64 + j * 16 + lr;
        b_off[j] = (uint32_t)row * 128;
        b_key[j] = (uint32_t)(row & 7) << 4;
    }

    float acc[2][8][4];
#pragma unroll
    for (int mt = 0; mt < 2; mt++)
#pragma unroll
        for (int nt = 0; nt < 8; nt++)
#pragma unroll
            for (int e = 0; e < 4; e++)
                acc[mt][nt][e] = 0.0f;

    // ---- pipeline: prefetch stage 0 and 1 ----
    load_stage(0, 0);
    load_stage(1, 1);

#pragma unroll 1
    for (int ck = 0; ck < NSTAGE; ck++) {
        if (ck < NSTAGE - 1) { CP_WAIT(1); } else { CP_WAIT(0); }
        __syncthreads();

        const uint32_t sb = smb + (uint32_t)(ck & 1) * STAGE_BYTES;
#pragma unroll
        for (int ks = 0; ks < 4; ks++) {
            const uint32_t kc16 = (uint32_t)(ks * 32 + cb * 16);
            uint32_t ah[2][4], al[2][4], bh[4][4], bl[4][4];
#pragma unroll
            for (int mt = 0; mt < 2; mt++) {
                uint32_t ax = a_off[mt] + (kc16 ^ a_key[mt]);
                ldmx4(ah[mt], sb + T_WH + ax);
                ldmx4(al[mt], sb + T_WL + ax);
            }
#pragma unroll
            for (int j = 0; j < 4; j++) {
                uint32_t bx = b_off[j] + (kc16 ^ b_key[j]);
                ldmx4(bh[j], sb + T_XH + bx);
                ldmx4(bl[j], sb + T_XL + bx);
            }
#pragma unroll
            for (int mt = 0; mt < 2; mt++) {
#pragma unroll
                for (int j = 0; j < 4; j++) {
                    // nt = 2j (rows n0-7 of x4) : frags [0],[2]
                    mma16816(acc[mt][2 * j], ah[mt], bh[j][0], bh[j][2]);
                    mma16816(acc[mt][2 * j], ah[mt], bl[j][0], bl[j][2]);
                    mma16816(acc[mt][2 * j], al[mt], bh[j][0], bh[j][2]);
                    // nt = 2j+1 (rows n8-15) : frags [1],[3]
                    mma16816(acc[mt][2 * j + 1], ah[mt], bh[j][1], bh[j][3]);
                    mma16816(acc[mt][2 * j + 1], ah[mt], bl[j][1], bl[j][3]);
                    mma16816(acc[mt][2 * j + 1], al[mt], bh[j][1], bh[j][3]);
                }
            }
        }
        __syncthreads();
        if (ck + 2 < NSTAGE) load_stage(ck + 2, ck & 1);
    }

    // ---- epilogue: coalesced float2 stores to px-major scratch ----
    const int g  = lid >> 2;
    const int tq = lid & 3;
    float* tb = g_tmp + ((size_t)(b * 16 + phase) * COUT + o0) * NPX + px0;
#pragma unroll
    for (int mt = 0; mt < 2; mt++) {
#pragma unroll
        for (int nt = 0; nt < 8; nt++) {
            int o  = mw * 32 + mt * 16 + g;
            int px = nw * 64 + nt * 8 + tq * 2;
            float2 v0 = make_float2(acc[mt][nt][0], acc[mt][nt][1]);
            float2 v1 = make_float2(acc[mt][nt][2], acc[mt][nt][3]);
            *reinterpret_cast<float2*>(tb + (size_t)o * NPX + px)       = v0;
            *reinterpret_cast<float2*>(tb + (size_t)(o + 8) * NPX + px) = v1;
        }
    }
}

// ============================================================================
// Pass 3: unshuffle g_tmp[b][phase][o][px] -> out[b][o][h][w]
//   block = one (b,o) plane: 16 phases x 256 px -> 64x64 image
// ============================================================================
__global__ __launch_bounds__(256)
void unshuffle_kernel(float* __restrict__ out) {
    __shared__ float s[4096];
    const int t  = threadIdx.x;
    const int o  = blockIdx.x & 511;
    const int b  = blockIdx.x >> 9;

    const float* src = g_tmp + (size_t)b * 16 * COUT * NPX + (size_t)o * NPX;
#pragma unroll
    for (int i = 0; i < 4; i++) {
        int gi = t + i * 256;          // 0..1023 float4s
        int ph = gi >> 6, f4 = gi & 63;
        float4 v = *reinterpret_cast<const float4*>(src + (size_t)ph * COUT * NPX + f4 * 4);
        *reinterpret_cast<float4*>(&s[ph * 256 + f4 * 4]) = v;
    }
    __syncthreads();

    const int h  = t >> 2;
    const int wb = (t & 3) * 16;
    const int r  = h & 3;
    const int h4 = h >> 2;
    float* dst = out + ((size_t)(b * COUT + o) * 64 + h) * 64 + wb;
#pragma unroll
    for (int k4 = 0; k4 < 4; k4++) {
        int w4 = (wb >> 2) + k4;
        float4 v;
        v.x = s[(r * 4 + 0) * 256 + h4 * 16 + w4];
        v.y = s[(r * 4 + 1) * 256 + h4 * 16 + w4];
        v.z = s[(r * 4 + 2) * 256 + h4 * 16 + w4];
        v.w = s[(r * 4 + 3) * 256 + h4 * 16 + w4];
        *reinterpret_cast<float4*>(dst + k4 * 4) = v;
    }
}

// ============================================================================
extern "C" void kernel_launch(void* const* d_in, const int* in_sizes, int n_in,
                              void* d_out, int out_size)
{
    const float* x  = (const float*)d_in[0];   // [16, 512, 64, 64]
    const float* Wg = (const float*)d_in[1];   // [16, 512, 512]
    float* out = (float*)d_out;                // [16, 512, 64, 64]

    cudaFuncSetAttribute(gwlp_mma_kernel,
                         cudaFuncAttributeMaxDynamicSharedMemorySize, 2 * STAGE_BYTES);

    convert_w_kernel<<<2048, 256>>>(Wg);
    convert_x_kernel<<<8192, 256>>>(x);
    gwlp_mma_kernel<<<2048, 256, 2 * STAGE_BYTES>>>();
    unshuffle_kernel<<<8192, 256>>>(out);
}